// round 16
// baseline (speedup 1.0000x reference)
#include <cuda_runtime.h>

#define BS    2048
#define NINP  512
#define NHID  512
#define TT    8
#define MM    32
#define NTOT  32768
#define GI_COLS 768
#define NPAIR (NTOT/2)   // 16384

typedef unsigned long long u64;
typedef unsigned int u32;

// device scratch
__device__ float g_gi[BS * GI_COLS];            // 6 MB
__device__ float g_hn[TT * NTOT * MM];          // hnext, 32 MB (L2-resident)

// ---- packed f32x2 helpers --------------------------------------------------
__device__ __forceinline__ void fma2(u64& acc, u64 a, u64 b) {
    asm("fma.rn.f32x2 %0, %1, %2, %0;" : "+l"(acc) : "l"(a), "l"(b));
}
__device__ __forceinline__ u64 pk(float lo, float hi) {
    u64 r; asm("mov.b64 %0, {%1, %2};" : "=l"(r) : "f"(lo), "f"(hi)); return r;
}
__device__ __forceinline__ void unpk(float& lo, float& hi, u64 v) {
    asm("mov.b64 {%0, %1}, %2;" : "=f"(lo), "=f"(hi) : "l"(v));
}
__device__ __forceinline__ float hadd(u64 v) {
    float a, b; unpk(a, b, v); return a + b;
}

// ---------------------------------------------------------------------------
// Kernel 1: gi = x @ W_ih^T + b_ih. (verified r15, unchanged)
// ---------------------------------------------------------------------------
#define SG 68

__global__ void __launch_bounds__(128) gemm_gi_kernel(
    const float* __restrict__ A,
    const float* __restrict__ B,
    const float* __restrict__ bias)
{
    __shared__ float As[2][32 * SG];
    __shared__ float Bs[2][32 * SG];

    const int tid = threadIdx.x;
    const int tx  = tid & 7;
    const int ty  = tid >> 3;
    const int n0  = blockIdx.x * 64;
    const int m0  = blockIdx.y * 64;

    float4 ra[4], rb[4];

    #define LDG_CHUNK(c) {                                                    \
        const int kb_ = (c) * 32;                                             \
        _Pragma("unroll")                                                     \
        for (int i_ = 0; i_ < 4; i_++) {                                      \
            int idx_ = tid + 128 * i_;                                        \
            int r_ = idx_ >> 3, c4_ = (idx_ & 7) * 4;                         \
            ra[i_] = *(const float4*)&A[(m0 + r_) * NINP + kb_ + c4_];        \
            rb[i_] = *(const float4*)&B[(n0 + r_) * NINP + kb_ + c4_];        \
        }                                                                     \
    }

    #define STS_CHUNK(buf) {                                                  \
        _Pragma("unroll")                                                     \
        for (int i_ = 0; i_ < 4; i_++) {                                      \
            int idx_ = tid + 128 * i_;                                        \
            int r_ = idx_ >> 3, kc_ = (idx_ & 7) * 4;                         \
            As[buf][(kc_ + 0) * SG + r_] = ra[i_].x;                          \
            As[buf][(kc_ + 1) * SG + r_] = ra[i_].y;                          \
            As[buf][(kc_ + 2) * SG + r_] = ra[i_].z;                          \
            As[buf][(kc_ + 3) * SG + r_] = ra[i_].w;                          \
            Bs[buf][(kc_ + 0) * SG + r_] = rb[i_].x;                          \
            Bs[buf][(kc_ + 1) * SG + r_] = rb[i_].y;                          \
            Bs[buf][(kc_ + 2) * SG + r_] = rb[i_].z;                          \
            Bs[buf][(kc_ + 3) * SG + r_] = rb[i_].w;                          \
        }                                                                     \
    }

    u64 acc[2][8];
#pragma unroll
    for (int i = 0; i < 2; i++)
#pragma unroll
        for (int j = 0; j < 8; j++) acc[i][j] = 0ull;

    LDG_CHUNK(0);
    STS_CHUNK(0);
    LDG_CHUNK(1);
    __syncthreads();

#pragma unroll 1
    for (int c = 0; c < 16; c++) {
        const int buf = c & 1;
        if (c < 15) STS_CHUNK(buf ^ 1);
        if (c < 14) LDG_CHUNK(c + 2);

        const float* Ab = As[buf];
        const float* Bb = Bs[buf];
#pragma unroll
        for (int k = 0; k < 32; k++) {
            ulonglong2 a2 = *(const ulonglong2*)(Ab + k * SG + ty * 4);
            float4 b1 = *(const float4*)(Bb + k * SG + tx * 4);
            float4 b2 = *(const float4*)(Bb + k * SG + 32 + tx * 4);
            u64 bb[8];
            bb[0] = pk(b1.x, b1.x); bb[1] = pk(b1.y, b1.y);
            bb[2] = pk(b1.z, b1.z); bb[3] = pk(b1.w, b1.w);
            bb[4] = pk(b2.x, b2.x); bb[5] = pk(b2.y, b2.y);
            bb[6] = pk(b2.z, b2.z); bb[7] = pk(b2.w, b2.w);
#pragma unroll
            for (int j = 0; j < 8; j++) {
                fma2(acc[0][j], a2.x, bb[j]);
                fma2(acc[1][j], a2.y, bb[j]);
            }
        }
        __syncthreads();
    }

    float4 bj1 = *(const float4*)&bias[n0 + tx * 4];
    float4 bj2 = *(const float4*)&bias[n0 + 32 + tx * 4];
#pragma unroll
    for (int p = 0; p < 2; p++) {
        int mrow = m0 + ty * 4 + p * 2;
        float lo[8], hi[8];
#pragma unroll
        for (int j = 0; j < 8; j++) unpk(lo[j], hi[j], acc[p][j]);
        *(float4*)&g_gi[mrow * GI_COLS + n0 + tx * 4] =
            make_float4(lo[0] + bj1.x, lo[1] + bj1.y, lo[2] + bj1.z, lo[3] + bj1.w);
        *(float4*)&g_gi[mrow * GI_COLS + n0 + 32 + tx * 4] =
            make_float4(lo[4] + bj2.x, lo[5] + bj2.y, lo[6] + bj2.z, lo[7] + bj2.w);
        *(float4*)&g_gi[(mrow + 1) * GI_COLS + n0 + tx * 4] =
            make_float4(hi[0] + bj1.x, hi[1] + bj1.y, hi[2] + bj1.z, hi[3] + bj1.w);
        *(float4*)&g_gi[(mrow + 1) * GI_COLS + n0 + 32 + tx * 4] =
            make_float4(hi[4] + bj2.x, hi[5] + bj2.y, hi[6] + bj2.z, hi[7] + bj2.w);
    }
    #undef LDG_CHUNK
    #undef STS_CHUNK
}

// ---------------------------------------------------------------------------
// Kernel A: gates + hnext ONLY (attention moved to select).
// Pair-of-n per thread, 224 thr, 2 blocks/SM (146-reg cap, 14 warps).
// ---------------------------------------------------------------------------
#define PT 224
__global__ void __launch_bounds__(PT, 2) gates_kernel(
    const float* __restrict__ h,
    const float* __restrict__ W_hh,
    const float* __restrict__ b_hh)
{
    __shared__ float Wg[96 * 32];    // this template's gate weights 12 KB
    __shared__ float bs[96];

    const int tid = threadIdx.x;
    const int t   = blockIdx.y;

    {
        const float4* s1 = (const float4*)(W_hh + t * 96 * 32);
        float4* d1 = (float4*)Wg;
        for (int i = tid; i < 768; i += PT) d1[i] = s1[i];
        if (tid < 24) ((float4*)bs)[tid] = ((const float4*)(b_hh + t * 96))[tid];
    }
    __syncthreads();

    const int p = blockIdx.x * PT + tid;
    if (p >= NPAIR) return;
    const int b  = p >> 3;
    const int n1 = b * 16 + (p & 7);
    const int n2 = n1 + 8;

    u64 hA[16], hB[16];
    {
        const ulonglong2* h1 = (const ulonglong2*)(h + n1 * MM);
        const ulonglong2* h2 = (const ulonglong2*)(h + n2 * MM);
#pragma unroll
        for (int q = 0; q < 8; q++) {
            ulonglong2 v = h1[q]; hA[2*q] = v.x; hA[2*q+1] = v.y;
            ulonglong2 w = h2[q]; hB[2*q] = w.x; hB[2*q+1] = w.y;
        }
    }

    const float* gib = g_gi + b * GI_COLS + t * 96;
    float* ho1 = g_hn + (t * (size_t)NTOT + n1) * MM;
    float* ho2 = g_hn + (t * (size_t)NTOT + n2) * MM;

#pragma unroll 1
    for (int l4 = 0; l4 < 8; l4++) {
        float Ga[4], Gb[4], Gc[4];
        *(float4*)Ga = *(const float4*)(gib + 4*l4);
        *(float4*)Gb = *(const float4*)(gib + 32 + 4*l4);
        *(float4*)Gc = *(const float4*)(gib + 64 + 4*l4);
        float o1[4], o2[4];
#pragma unroll
        for (int li = 0; li < 4; li++) {
            const int l = 4*l4 + li;
            const ulonglong2* wr = (const ulonglong2*)(Wg + l * 32);
            const ulonglong2* wz = (const ulonglong2*)(Wg + (32 + l) * 32);
            const ulonglong2* wn = (const ulonglong2*)(Wg + (64 + l) * 32);
            u64 aR1 = pk(bs[l],      0.f), aR2 = aR1;
            u64 aZ1 = pk(bs[32 + l], 0.f), aZ2 = aZ1;
            u64 aN1 = pk(bs[64 + l], 0.f), aN2 = aN1;
#pragma unroll
            for (int q = 0; q < 8; q++) {
                ulonglong2 wa = wr[q];
                fma2(aR1, wa.x, hA[2*q]); fma2(aR1, wa.y, hA[2*q+1]);
                fma2(aR2, wa.x, hB[2*q]); fma2(aR2, wa.y, hB[2*q+1]);
            }
#pragma unroll
            for (int q = 0; q < 8; q++) {
                ulonglong2 wb = wz[q];
                fma2(aZ1, wb.x, hA[2*q]); fma2(aZ1, wb.y, hA[2*q+1]);
                fma2(aZ2, wb.x, hB[2*q]); fma2(aZ2, wb.y, hB[2*q+1]);
            }
#pragma unroll
            for (int q = 0; q < 8; q++) {
                ulonglong2 wc = wn[q];
                fma2(aN1, wc.x, hA[2*q]); fma2(aN1, wc.y, hA[2*q+1]);
                fma2(aN2, wc.x, hB[2*q]); fma2(aN2, wc.y, hB[2*q+1]);
            }
            {
                float ar = hadd(aR1), az = hadd(aZ1), an = hadd(aN1);
                float lo, hi; unpk(lo, hi, hA[l >> 1]); float hl = (l & 1) ? hi : lo;
                float r  = __fdividef(1.f, 1.f + __expf(-(Ga[li] + ar)));
                float z  = __fdividef(1.f, 1.f + __expf(-(Gb[li] + az)));
                float xn = Gc[li] + r * an;
                float e2 = __expf(-2.f * xn);
                float nn = __fdividef(1.f - e2, 1.f + e2);
                o1[li] = (1.f - z) * nn + z * hl;
            }
            {
                float ar = hadd(aR2), az = hadd(aZ2), an = hadd(aN2);
                float lo, hi; unpk(lo, hi, hB[l >> 1]); float hl = (l & 1) ? hi : lo;
                float r  = __fdividef(1.f, 1.f + __expf(-(Ga[li] + ar)));
                float z  = __fdividef(1.f, 1.f + __expf(-(Gb[li] + az)));
                float xn = Gc[li] + r * an;
                float e2 = __expf(-2.f * xn);
                float nn = __fdividef(1.f - e2, 1.f + e2);
                o2[li] = (1.f - z) * nn + z * hl;
            }
        }
        *(float4*)(ho1 + 4*l4) = *(float4*)o1;
        *(float4*)(ho2 + 4*l4) = *(float4*)o2;
    }
}

// ---------------------------------------------------------------------------
// Kernel B: attention logits (from g_hn) + gumbel softmax + select + outputs.
// Thread-per-n, 128 thr x 256 blocks. hr computed in-thread; av-form
// attention with w_write warp-uniform from smem (r11-verified pattern).
// ---------------------------------------------------------------------------
__global__ void __launch_bounds__(128) select_kernel(
    const float* __restrict__ h,
    const float* __restrict__ w_read,
    const float* __restrict__ w_write,
    const float* __restrict__ gum,
    float* __restrict__ out)
{
    __shared__ float Wr[512];        // w_read [32][16]
    __shared__ float Ww[4096];       // w_write [8][32][16]
    const int tid = threadIdx.x;
    if (tid < 128) ((float4*)Wr)[tid] = ((const float4*)w_read)[tid];
    for (int i = tid; i < 1024; i += 128)
        ((float4*)Ww)[i] = ((const float4*)w_write)[i];
    __syncthreads();

    const int n = blockIdx.x * 128 + tid;

    // h_read (verified hr code: m-sequential fmaf)
    float hr[16];
    {
        float h2[32];
        const float4* hp = (const float4*)(h + n * MM);
#pragma unroll
        for (int i = 0; i < 8; i++) {
            float4 v = hp[i];
            h2[4*i] = v.x; h2[4*i+1] = v.y; h2[4*i+2] = v.z; h2[4*i+3] = v.w;
        }
#pragma unroll
        for (int f = 0; f < 16; f++) hr[f] = 0.f;
#pragma unroll 4
        for (int m = 0; m < 32; m++) {
            const float4* w = (const float4*)(Wr + m * 16);
            float hm = h2[m];
#pragma unroll
            for (int f4 = 0; f4 < 4; f4++) {
                float4 v = w[f4];
                hr[4*f4]   = fmaf(hm, v.x, hr[4*f4]);
                hr[4*f4+1] = fmaf(hm, v.y, hr[4*f4+1]);
                hr[4*f4+2] = fmaf(hm, v.z, hr[4*f4+2]);
                hr[4*f4+3] = fmaf(hm, v.w, hr[4*f4+3]);
            }
        }
    }
    // pack hr into f-pairs
    u64 hrp[8];
#pragma unroll
    for (int f2 = 0; f2 < 8; f2++) hrp[f2] = pk(hr[2*f2], hr[2*f2+1]);

    // gumbel prefetch
    float g8[8];
    {
        const float4* gp = (const float4*)(gum + n * TT);
        float4 a = gp[0], c = gp[1];
        g8[0]=a.x; g8[1]=a.y; g8[2]=a.z; g8[3]=a.w;
        g8[4]=c.x; g8[5]=c.y; g8[6]=c.z; g8[7]=c.w;
    }

    float s[8];
#pragma unroll 1
    for (int t = 0; t < TT; t++) {
        // load hnext[t][n][*]
        float hn[32];
        {
            const float4* hp = (const float4*)(g_hn + (t * (size_t)NTOT + n) * MM);
#pragma unroll
            for (int i = 0; i < 8; i++) {
                float4 v = hp[i];
                hn[4*i] = v.x; hn[4*i+1] = v.y; hn[4*i+2] = v.z; hn[4*i+3] = v.w;
            }
        }
        const float* wwt = Ww + t * MM * 16;
        float lg = 0.f;
#pragma unroll 4
        for (int l = 0; l < 32; l++) {
            const ulonglong2* ww = (const ulonglong2*)(wwt + l * 16);
            ulonglong2 w0 = ww[0], w1 = ww[1];
            u64 aA = 0ull;
            fma2(aA, w0.x, hrp[0]); fma2(aA, w0.y, hrp[1]);
            fma2(aA, w1.x, hrp[2]); fma2(aA, w1.y, hrp[3]);
            ulonglong2 w2 = ww[2], w3 = ww[3];
            fma2(aA, w2.x, hrp[4]); fma2(aA, w2.y, hrp[5]);
            fma2(aA, w3.x, hrp[6]); fma2(aA, w3.y, hrp[7]);
            lg = fmaf(hn[l], hadd(aA), lg);
        }
        s[t] = (lg + g8[t]) * 2.0f;          // /TAU, TAU=0.5
    }

    float smax = s[0];
    int amax = 0;
#pragma unroll
    for (int t = 1; t < 8; t++)
        if (s[t] > smax) { smax = s[t]; amax = t; }
    float sum = 0.f;
#pragma unroll
    for (int t = 0; t < 8; t++) sum += __expf(s[t] - smax);

    float p = __fdividef(1.f, sum);          // softmax at argmax
    float attv = (1.f + p) - p;              // straight-through residual, exact

    const float4* hp = (const float4*)(g_hn + (amax * (size_t)NTOT + n) * MM);
    float4* ho = (float4*)(out + n * MM);
#pragma unroll
    for (int i = 0; i < 8; i++) {
        float4 v = hp[i];
        v.x *= attv; v.y *= attv; v.z *= attv; v.w *= attv;
        ho[i] = v;
    }
    float* ao = out + BS * NHID + n * TT;
#pragma unroll
    for (int t = 0; t < 8; t++) ao[t] = (t == amax) ? attv : 0.f;
}

// ---------------------------------------------------------------------------
extern "C" void kernel_launch(void* const* d_in, const int* in_sizes, int n_in,
                              void* d_out, int out_size)
{
    const float* x       = (const float*)d_in[0];
    const float* h       = (const float*)d_in[1];
    const float* W_ih    = (const float*)d_in[2];
    const float* W_hh    = (const float*)d_in[3];
    const float* b_ih    = (const float*)d_in[4];
    const float* b_hh    = (const float*)d_in[5];
    const float* w_read  = (const float*)d_in[6];
    const float* w_write = (const float*)d_in[7];
    const float* gum     = (const float*)d_in[8];
    float* out = (float*)d_out;

    dim3 g1(GI_COLS / 64, BS / 64);                   // (12, 32) = 384
    gemm_gi_kernel<<<g1, 128>>>(x, W_ih, b_ih);

    dim3 g2((NPAIR + PT - 1) / PT, TT);               // (74, 8)
    gates_kernel<<<g2, PT>>>(h, W_hh, b_hh);

    select_kernel<<<NTOT / 128, 128>>>(h, w_read, w_write, gum, out);
}

// round 17
// speedup vs baseline: 1.0143x; 1.0143x over previous
#include <cuda_runtime.h>

#define BS    2048
#define NINP  512
#define NHID  512
#define TT    8
#define MM    32
#define NTOT  32768
#define GI_COLS 768
#define NPAIR (NTOT/2)   // 16384

typedef unsigned long long u64;
typedef unsigned int u32;

// device scratch
__device__ float g_gi[BS * GI_COLS];            // 6 MB
__device__ float g_gip2[2][BS * GI_COLS];       // gemm partials, 12 MB
__device__ float g_hn[TT * NTOT * MM];          // hnext, 32 MB
__device__ float g_lg[NTOT * TT];               // logits, 1 MB
__device__ float g_av[64 * NTOT * 4];           // av transposed [t*8+l4][n][4], 33 MB

// ---- packed f32x2 helpers --------------------------------------------------
__device__ __forceinline__ void fma2(u64& acc, u64 a, u64 b) {
    asm("fma.rn.f32x2 %0, %1, %2, %0;" : "+l"(acc) : "l"(a), "l"(b));
}
__device__ __forceinline__ u64 pk(float lo, float hi) {
    u64 r; asm("mov.b64 %0, {%1, %2};" : "=l"(r) : "f"(lo), "f"(hi)); return r;
}
__device__ __forceinline__ void unpk(float& lo, float& hi, u64 v) {
    asm("mov.b64 {%0, %1}, %2;" : "=f"(lo), "=f"(hi) : "l"(v));
}
__device__ __forceinline__ float hadd(u64 v) {
    float a, b; unpk(a, b, v); return a + b;
}

// ---------------------------------------------------------------------------
// Kernel 1: gi partials = x @ W_ih^T, k-split x2 (verified r15 body, z-split).
// 64x64 tile, 128 threads, m-paired FFMA2, grid 768 -> >=4 blocks/SM.
// ---------------------------------------------------------------------------
#define SG 68

__global__ void __launch_bounds__(128, 4) gemm_gi_kernel(
    const float* __restrict__ A,
    const float* __restrict__ B)
{
    __shared__ float As[2][32 * SG];
    __shared__ float Bs[2][32 * SG];

    const int tid = threadIdx.x;
    const int tx  = tid & 7;
    const int ty  = tid >> 3;
    const int n0  = blockIdx.x * 64;
    const int m0  = blockIdx.y * 64;
    const int kb0 = blockIdx.z * 256;

    float4 ra[4], rb[4];

    #define LDG_CHUNK(c) {                                                    \
        const int kb_ = kb0 + (c) * 32;                                       \
        _Pragma("unroll")                                                     \
        for (int i_ = 0; i_ < 4; i_++) {                                      \
            int idx_ = tid + 128 * i_;                                        \
            int r_ = idx_ >> 3, c4_ = (idx_ & 7) * 4;                         \
            ra[i_] = *(const float4*)&A[(m0 + r_) * NINP + kb_ + c4_];        \
            rb[i_] = *(const float4*)&B[(n0 + r_) * NINP + kb_ + c4_];        \
        }                                                                     \
    }

    #define STS_CHUNK(buf) {                                                  \
        _Pragma("unroll")                                                     \
        for (int i_ = 0; i_ < 4; i_++) {                                      \
            int idx_ = tid + 128 * i_;                                        \
            int r_ = idx_ >> 3, kc_ = (idx_ & 7) * 4;                         \
            As[buf][(kc_ + 0) * SG + r_] = ra[i_].x;                          \
            As[buf][(kc_ + 1) * SG + r_] = ra[i_].y;                          \
            As[buf][(kc_ + 2) * SG + r_] = ra[i_].z;                          \
            As[buf][(kc_ + 3) * SG + r_] = ra[i_].w;                          \
            Bs[buf][(kc_ + 0) * SG + r_] = rb[i_].x;                          \
            Bs[buf][(kc_ + 1) * SG + r_] = rb[i_].y;                          \
            Bs[buf][(kc_ + 2) * SG + r_] = rb[i_].z;                          \
            Bs[buf][(kc_ + 3) * SG + r_] = rb[i_].w;                          \
        }                                                                     \
    }

    u64 acc[2][8];
#pragma unroll
    for (int i = 0; i < 2; i++)
#pragma unroll
        for (int j = 0; j < 8; j++) acc[i][j] = 0ull;

    LDG_CHUNK(0);
    STS_CHUNK(0);
    LDG_CHUNK(1);
    __syncthreads();

#pragma unroll 1
    for (int c = 0; c < 8; c++) {
        const int buf = c & 1;
        if (c < 7) STS_CHUNK(buf ^ 1);
        if (c < 6) LDG_CHUNK(c + 2);

        const float* Ab = As[buf];
        const float* Bb = Bs[buf];
#pragma unroll
        for (int k = 0; k < 32; k++) {
            ulonglong2 a2 = *(const ulonglong2*)(Ab + k * SG + ty * 4);
            float4 b1 = *(const float4*)(Bb + k * SG + tx * 4);
            float4 b2 = *(const float4*)(Bb + k * SG + 32 + tx * 4);
            u64 bb[8];
            bb[0] = pk(b1.x, b1.x); bb[1] = pk(b1.y, b1.y);
            bb[2] = pk(b1.z, b1.z); bb[3] = pk(b1.w, b1.w);
            bb[4] = pk(b2.x, b2.x); bb[5] = pk(b2.y, b2.y);
            bb[6] = pk(b2.z, b2.z); bb[7] = pk(b2.w, b2.w);
#pragma unroll
            for (int j = 0; j < 8; j++) {
                fma2(acc[0][j], a2.x, bb[j]);
                fma2(acc[1][j], a2.y, bb[j]);
            }
        }
        __syncthreads();
    }

    float* gp = g_gip2[blockIdx.z];
#pragma unroll
    for (int p = 0; p < 2; p++) {
        int mrow = m0 + ty * 4 + p * 2;
        float lo[8], hi[8];
#pragma unroll
        for (int j = 0; j < 8; j++) unpk(lo[j], hi[j], acc[p][j]);
        *(float4*)&gp[mrow * GI_COLS + n0 + tx * 4] =
            make_float4(lo[0], lo[1], lo[2], lo[3]);
        *(float4*)&gp[mrow * GI_COLS + n0 + 32 + tx * 4] =
            make_float4(lo[4], lo[5], lo[6], lo[7]);
        *(float4*)&gp[(mrow + 1) * GI_COLS + n0 + tx * 4] =
            make_float4(hi[0], hi[1], hi[2], hi[3]);
        *(float4*)&gp[(mrow + 1) * GI_COLS + n0 + 32 + tx * 4] =
            make_float4(hi[4], hi[5], hi[6], hi[7]);
    }
    #undef LDG_CHUNK
    #undef STS_CHUNK
}

// ---------------------------------------------------------------------------
// Kernel 1b: reduce 2 partials + bias -> g_gi
// ---------------------------------------------------------------------------
__global__ void __launch_bounds__(256) reduce_gi_kernel(
    const float* __restrict__ bias)
{
    int i = blockIdx.x * 256 + threadIdx.x;
    int col = (i * 4) % GI_COLS;
    float4 b = *(const float4*)&bias[col];
    float4 s0 = *(const float4*)&g_gip2[0][i * 4];
    float4 s1 = *(const float4*)&g_gip2[1][i * 4];
    float4 r;
    r.x = (s0.x + s1.x) + b.x;
    r.y = (s0.y + s1.y) + b.y;
    r.z = (s0.z + s1.z) + b.z;
    r.w = (s0.w + s1.w) + b.w;
    *(float4*)&g_gi[i * 4] = r;
}

// ---------------------------------------------------------------------------
// Kernel 1c: h_read + av precompute (verified r12 hrav, unchanged).
// g_av[((t*8+l4)*NTOT + n)*4 + li] = w_write[t][l4*4+li] . h_read[n]
// ---------------------------------------------------------------------------
__global__ void __launch_bounds__(256) hrav_kernel(
    const float* __restrict__ h,
    const float* __restrict__ w_read,
    const float* __restrict__ w_write)
{
    __shared__ float Wr[512];
    __shared__ float Ww[4096];
    const int tid = threadIdx.x;
    if (tid < 128) ((float4*)Wr)[tid] = ((const float4*)w_read)[tid];
    for (int i = tid; i < 1024; i += 256)
        ((float4*)Ww)[i] = ((const float4*)w_write)[i];
    __syncthreads();

    const int n = blockIdx.x * 256 + tid;

    float h2[32];
    {
        const float4* hp = (const float4*)(h + n * MM);
#pragma unroll
        for (int i = 0; i < 8; i++) {
            float4 v = hp[i];
            h2[4*i] = v.x; h2[4*i+1] = v.y; h2[4*i+2] = v.z; h2[4*i+3] = v.w;
        }
    }
    float hr[16];
#pragma unroll
    for (int f = 0; f < 16; f++) hr[f] = 0.f;
#pragma unroll 4
    for (int m = 0; m < 32; m++) {
        const float4* w = (const float4*)(Wr + m * 16);
        float hm = h2[m];
#pragma unroll
        for (int f4 = 0; f4 < 4; f4++) {
            float4 v = w[f4];
            hr[4*f4]   = fmaf(hm, v.x, hr[4*f4]);
            hr[4*f4+1] = fmaf(hm, v.y, hr[4*f4+1]);
            hr[4*f4+2] = fmaf(hm, v.z, hr[4*f4+2]);
            hr[4*f4+3] = fmaf(hm, v.w, hr[4*f4+3]);
        }
    }

#pragma unroll 1
    for (int t = 0; t < TT; t++) {
#pragma unroll 1
        for (int l4 = 0; l4 < 8; l4++) {
            float o[4];
#pragma unroll
            for (int li = 0; li < 4; li++) {
                const float* w = Ww + (t * 32 + l4 * 4 + li) * 16;
                float av = 0.f;
#pragma unroll
                for (int f = 0; f < 16; f++) av = fmaf(w[f], hr[f], av);
                o[li] = av;
            }
            *(float4*)&g_av[((size_t)(t * 8 + l4) * NTOT + n) * 4] = *(float4*)o;
        }
    }
}

// ---------------------------------------------------------------------------
// Kernel A: gates + hnext + cheap logit (av loaded from g_av).
// Pair-of-n per thread, 224 thr, 2 blocks/SM -> 14 warps/SM.
// ---------------------------------------------------------------------------
#define PT 224
__global__ void __launch_bounds__(PT, 2) gates_kernel(
    const float* __restrict__ h,
    const float* __restrict__ W_hh,
    const float* __restrict__ b_hh)
{
    __shared__ float Wg[96 * 32];
    __shared__ float bs[96];

    const int tid = threadIdx.x;
    const int t   = blockIdx.y;

    {
        const float4* s1 = (const float4*)(W_hh + t * 96 * 32);
        float4* d1 = (float4*)Wg;
        for (int i = tid; i < 768; i += PT) d1[i] = s1[i];
        if (tid < 24) ((float4*)bs)[tid] = ((const float4*)(b_hh + t * 96))[tid];
    }
    __syncthreads();

    const int p = blockIdx.x * PT + tid;
    if (p >= NPAIR) return;
    const int b  = p >> 3;
    const int n1 = b * 16 + (p & 7);
    const int n2 = n1 + 8;

    u64 hA[16], hB[16];
    {
        const ulonglong2* h1 = (const ulonglong2*)(h + n1 * MM);
        const ulonglong2* h2 = (const ulonglong2*)(h + n2 * MM);
#pragma unroll
        for (int q = 0; q < 8; q++) {
            ulonglong2 v = h1[q]; hA[2*q] = v.x; hA[2*q+1] = v.y;
            ulonglong2 w = h2[q]; hB[2*q] = w.x; hB[2*q+1] = w.y;
        }
    }

    const float* gib = g_gi + b * GI_COLS + t * 96;
    float* ho1 = g_hn + (t * (size_t)NTOT + n1) * MM;
    float* ho2 = g_hn + (t * (size_t)NTOT + n2) * MM;
    float lg1 = 0.f, lg2 = 0.f;

#pragma unroll 1
    for (int l4 = 0; l4 < 8; l4++) {
        float Ga[4], Gb[4], Gc[4], av1[4], av2[4];
        *(float4*)Ga = *(const float4*)(gib + 4*l4);
        *(float4*)Gb = *(const float4*)(gib + 32 + 4*l4);
        *(float4*)Gc = *(const float4*)(gib + 64 + 4*l4);
        *(float4*)av1 = *(const float4*)&g_av[((size_t)(t * 8 + l4) * NTOT + n1) * 4];
        *(float4*)av2 = *(const float4*)&g_av[((size_t)(t * 8 + l4) * NTOT + n2) * 4];
        float o1[4], o2[4];
#pragma unroll
        for (int li = 0; li < 4; li++) {
            const int l = 4*l4 + li;
            const ulonglong2* wr = (const ulonglong2*)(Wg + l * 32);
            const ulonglong2* wz = (const ulonglong2*)(Wg + (32 + l) * 32);
            const ulonglong2* wn = (const ulonglong2*)(Wg + (64 + l) * 32);
            u64 aR1 = pk(bs[l],      0.f), aR2 = aR1;
            u64 aZ1 = pk(bs[32 + l], 0.f), aZ2 = aZ1;
            u64 aN1 = pk(bs[64 + l], 0.f), aN2 = aN1;
#pragma unroll
            for (int q = 0; q < 8; q++) {
                ulonglong2 wa = wr[q];
                fma2(aR1, wa.x, hA[2*q]); fma2(aR1, wa.y, hA[2*q+1]);
                fma2(aR2, wa.x, hB[2*q]); fma2(aR2, wa.y, hB[2*q+1]);
            }
#pragma unroll
            for (int q = 0; q < 8; q++) {
                ulonglong2 wb = wz[q];
                fma2(aZ1, wb.x, hA[2*q]); fma2(aZ1, wb.y, hA[2*q+1]);
                fma2(aZ2, wb.x, hB[2*q]); fma2(aZ2, wb.y, hB[2*q+1]);
            }
#pragma unroll
            for (int q = 0; q < 8; q++) {
                ulonglong2 wc = wn[q];
                fma2(aN1, wc.x, hA[2*q]); fma2(aN1, wc.y, hA[2*q+1]);
                fma2(aN2, wc.x, hB[2*q]); fma2(aN2, wc.y, hB[2*q+1]);
            }
            {
                float ar = hadd(aR1), az = hadd(aZ1), an = hadd(aN1);
                float lo, hi; unpk(lo, hi, hA[l >> 1]); float hl = (l & 1) ? hi : lo;
                float r  = __fdividef(1.f, 1.f + __expf(-(Ga[li] + ar)));
                float z  = __fdividef(1.f, 1.f + __expf(-(Gb[li] + az)));
                float xn = Gc[li] + r * an;
                float e2 = __expf(-2.f * xn);
                float nn = __fdividef(1.f - e2, 1.f + e2);
                float hn = (1.f - z) * nn + z * hl;
                o1[li] = hn;
                lg1 = fmaf(hn, av1[li], lg1);
            }
            {
                float ar = hadd(aR2), az = hadd(aZ2), an = hadd(aN2);
                float lo, hi; unpk(lo, hi, hB[l >> 1]); float hl = (l & 1) ? hi : lo;
                float r  = __fdividef(1.f, 1.f + __expf(-(Ga[li] + ar)));
                float z  = __fdividef(1.f, 1.f + __expf(-(Gb[li] + az)));
                float xn = Gc[li] + r * an;
                float e2 = __expf(-2.f * xn);
                float nn = __fdividef(1.f - e2, 1.f + e2);
                float hn = (1.f - z) * nn + z * hl;
                o2[li] = hn;
                lg2 = fmaf(hn, av2[li], lg2);
            }
        }
        *(float4*)(ho1 + 4*l4) = *(float4*)o1;
        *(float4*)(ho2 + 4*l4) = *(float4*)o2;
    }
    g_lg[n1 * TT + t] = lg1;
    g_lg[n2 * TT + t] = lg2;
}

// ---------------------------------------------------------------------------
// Kernel B: gumbel softmax + hard select + gather + outputs (verified r11)
// ---------------------------------------------------------------------------
__global__ void __launch_bounds__(256) select_kernel(
    const float* __restrict__ gum,
    float* __restrict__ out)
{
    const int n = blockIdx.x * 256 + threadIdx.x;

    float s[8];
    {
        const float4* lp = (const float4*)(g_lg + n * TT);
        const float4* gp = (const float4*)(gum + n * TT);
        float4 l0 = lp[0], l1 = lp[1], g0 = gp[0], g1 = gp[1];
        s[0] = (l0.x + g0.x) * 2.f; s[1] = (l0.y + g0.y) * 2.f;
        s[2] = (l0.z + g0.z) * 2.f; s[3] = (l0.w + g0.w) * 2.f;
        s[4] = (l1.x + g1.x) * 2.f; s[5] = (l1.y + g1.y) * 2.f;
        s[6] = (l1.z + g1.z) * 2.f; s[7] = (l1.w + g1.w) * 2.f;
    }
    float smax = s[0];
    int amax = 0;
#pragma unroll
    for (int t = 1; t < 8; t++)
        if (s[t] > smax) { smax = s[t]; amax = t; }
    float sum = 0.f;
#pragma unroll
    for (int t = 0; t < 8; t++) sum += __expf(s[t] - smax);

    float p = __fdividef(1.f, sum);
    float attv = (1.f + p) - p;

    const float4* hp = (const float4*)(g_hn + (amax * (size_t)NTOT + n) * MM);
    float4* ho = (float4*)(out + n * MM);
#pragma unroll
    for (int i = 0; i < 8; i++) {
        float4 v = hp[i];
        v.x *= attv; v.y *= attv; v.z *= attv; v.w *= attv;
        ho[i] = v;
    }
    float* ao = out + BS * NHID + n * TT;
#pragma unroll
    for (int t = 0; t < 8; t++) ao[t] = (t == amax) ? attv : 0.f;
}

// ---------------------------------------------------------------------------
extern "C" void kernel_launch(void* const* d_in, const int* in_sizes, int n_in,
                              void* d_out, int out_size)
{
    const float* x       = (const float*)d_in[0];
    const float* h       = (const float*)d_in[1];
    const float* W_ih    = (const float*)d_in[2];
    const float* W_hh    = (const float*)d_in[3];
    const float* b_ih    = (const float*)d_in[4];
    const float* b_hh    = (const float*)d_in[5];
    const float* w_read  = (const float*)d_in[6];
    const float* w_write = (const float*)d_in[7];
    const float* gum     = (const float*)d_in[8];
    float* out = (float*)d_out;

    dim3 g1(GI_COLS / 64, BS / 64, 2);                // (12, 32, 2) = 768
    gemm_gi_kernel<<<g1, 128>>>(x, W_ih);
    reduce_gi_kernel<<<BS * GI_COLS / 4 / 256, 256>>>(b_ih);

    hrav_kernel<<<NTOT / 256, 256>>>(h, w_read, w_write);

    dim3 g2((NPAIR + PT - 1) / PT, TT);               // (74, 8)
    gates_kernel<<<g2, PT>>>(h, W_hh, b_hh);

    select_kernel<<<NTOT / 256, 256>>>(gum, out);
}